// round 12
// baseline (speedup 1.0000x reference)
#include <cuda_runtime.h>

#define G 128
#define TPB 256
#define T_STEPS 220
#define CSTRIDE 16   // float4s per slot: 256B -> spreads L2 slice hash bits
#define FULLM 0xffffffffu

#define BAR_SYNC(id, n)   asm volatile("bar.sync %0, %1;"   :: "r"(id), "r"(n) : "memory")
#define BAR_ARRIVE(id, n) asm volatile("bar.arrive %0, %1;" :: "r"(id), "r"(n) : "memory")

// Seqlock exchange buffers: {val0, val1, seq, seq} per CTA, 256B-strided
// (round-6 proven layout; data + flag in one 16B volatile load).
__device__ float4 g_h0buf[G * CSTRIDE];
__device__ float4 g_h1buf[G * CSTRIDE];
__device__ float4 g_h2buf[G * CSTRIDE];
__device__ float4 g_rbuf [G * CSTRIDE];

__device__ __forceinline__ void ldv4(const float4* p, float& a, float& b,
                                     unsigned& s0, unsigned& s1) {
    unsigned x, y;
    asm volatile("ld.volatile.global.v4.b32 {%0,%1,%2,%3}, [%4];"
                 : "=r"(x), "=r"(y), "=r"(s0), "=r"(s1) : "l"(p));
    a = __uint_as_float(x);
    b = __uint_as_float(y);
}
__device__ __forceinline__ void stv4(float4* p, float a, float b, unsigned s) {
    asm volatile("st.volatile.global.v4.b32 [%0], {%1,%2,%3,%4};"
                 :: "l"(p), "r"(__float_as_uint(a)), "r"(__float_as_uint(b)),
                    "r"(s), "r"(s));
}
__device__ __forceinline__ float wreduce(float v) {
#pragma unroll
    for (int m = 16; m >= 1; m >>= 1) v += __shfl_xor_sync(FULLM, v, m);
    return v;
}
__device__ __forceinline__ void wreduce2(float& a, float& b) {
#pragma unroll
    for (int m = 16; m >= 1; m >>= 1) {
        a += __shfl_xor_sync(FULLM, a, m);
        b += __shfl_xor_sync(FULLM, b, m);
    }
}
__device__ __forceinline__ void wreduce4(float& a, float& b, float& c, float& d) {
#pragma unroll
    for (int m = 16; m >= 1; m >>= 1) {
        a += __shfl_xor_sync(FULLM, a, m);
        b += __shfl_xor_sync(FULLM, b, m);
        c += __shfl_xor_sync(FULLM, c, m);
        d += __shfl_xor_sync(FULLM, d, m);
    }
}
__device__ __forceinline__ void wreduce5(float& a, float& b, float& c,
                                         float& d, float& e) {
#pragma unroll
    for (int m = 16; m >= 1; m >>= 1) {
        a += __shfl_xor_sync(FULLM, a, m);
        b += __shfl_xor_sync(FULLM, b, m);
        c += __shfl_xor_sync(FULLM, c, m);
        d += __shfl_xor_sync(FULLM, d, m);
        e += __shfl_xor_sync(FULLM, e, m);
    }
}
__device__ __forceinline__ float fsig(float x) {
    return __fdividef(1.0f, 1.0f + __expf(-x));
}
__device__ __forceinline__ float ftanh(float x) {
    return 1.0f - __fdividef(2.0f, __expf(2.0f * x) + 1.0f);
}
__device__ __forceinline__ float dot256(const float* w, const float* x, int lane) {
    const float4* w4 = (const float4*)w;
    const float4* x4 = (const float4*)x;
    float s = 0.f;
#pragma unroll
    for (int i = 0; i < 2; i++) {
        float4 a = w4[i * 32 + lane], b = x4[i * 32 + lane];
        s += a.x * b.x + a.y * b.y + a.z * b.z + a.w * b.w;
    }
    return s;
}
// One poll slot per lane; writes result into dst. No barrier inside.
__device__ __forceinline__ void pollslot(const float4* buf, float* dst,
                                         unsigned seq, int s) {
    const float4* p = buf + (size_t)s * CSTRIDE;
    float a, b;
    unsigned s0, s1;
    for (;;) {
        ldv4(p, a, b, s0, s1);
        if (__all_sync(FULLM, (s0 == seq) & (s1 == seq))) break;
    }
    dst[2 * s]     = a;
    dst[2 * s + 1] = b;
}

// SMEM layout (floats)
#define OFF_L0W   0       // 8 x 512  layer0 [Wih(:,0:256) | Whh]
#define OFF_WH1   4096    // 8 x 256
#define OFF_WH2   6144
#define OFF_WI1   8192
#define OFF_WI2   10240
#define OFF_W1R   12288   // 2 x 256
#define OFF_W2S   12800   // 33 x 256
#define OFF_TBL   21248   // 33 x 8 embed-projection table
#define OFF_H0S   21512   // 256
#define OFF_H1S   21768
#define OFF_H2S   22024
#define OFF_RS    22280
#define OFF_GT    22536   // 8
#define OFF_PA    22544   // 8
#define OFF_PB    22552
#define OFF_PC    22560
#define OFF_PRED  22568   // 33 (+pad)
#define OFF_BA    22604   // 8
#define OFF_BB    22612
#define OFF_BC    22620
#define OFF_B1R   22628   // 2
#define OFF_B2S   22630   // 33
#define SMEM_FLOATS 22664

__global__ void __launch_bounds__(TPB, 1)
speller_kernel(const float* __restrict__ embed_g,
               const float* __restrict__ Wih0,
               const float* __restrict__ Wihr,
               const float* __restrict__ Whh,
               const float* __restrict__ bih,
               const float* __restrict__ bhh,
               const float* __restrict__ W1,
               const float* __restrict__ b1,
               const float* __restrict__ W2,
               const float* __restrict__ b2,
               const float* __restrict__ h0in,
               const float* __restrict__ c0in,
               float* __restrict__ out)
{
    extern __shared__ float sm[];
    float* l0w  = sm + OFF_L0W;
    float* wh1  = sm + OFF_WH1;
    float* wh2  = sm + OFF_WH2;
    float* wi1  = sm + OFF_WI1;
    float* wi2  = sm + OFF_WI2;
    float* w1r  = sm + OFF_W1R;
    float* w2s  = sm + OFF_W2S;
    float* tbl  = sm + OFF_TBL;
    float* h0s  = sm + OFF_H0S;
    float* h1s  = sm + OFF_H1S;
    float* h2s  = sm + OFF_H2S;
    float* rs   = sm + OFF_RS;
    float* gT   = sm + OFF_GT;
    float* pA   = sm + OFF_PA;
    float* pB   = sm + OFF_PB;
    float* pC   = sm + OFF_PC;
    float* pred = sm + OFF_PRED;
    float* biasA = sm + OFF_BA;
    float* biasB = sm + OFF_BB;
    float* biasC = sm + OFF_BC;
    float* b1r  = sm + OFF_B1R;
    float* b2s  = sm + OFF_B2S;

    const int tid  = threadIdx.x;
    const int wid  = tid >> 5;
    const int lane = tid & 31;
    const int k    = blockIdx.x;
    const int j0   = 2 * k;          // this CTA's hidden-unit pair

    // ---- One-time weight staging (ctx columns are all-zero: dropped) ----
    // local gate row r = gate*2 + u  (i:0,1  f:2,3  g:4,5  o:6,7)
    for (int idx = tid; idx < 8 * 512; idx += TPB) {
        int r = idx >> 9, c = idx & 511;
        int rg = ((r >> 1) << 8) + j0 + (r & 1);
        l0w[idx] = (c < 256) ? Wih0[rg * 384 + c] : Whh[rg * 256 + (c - 256)];
    }
    for (int idx = tid; idx < 8 * 256; idx += TPB) {
        int r = idx >> 8, c = idx & 255;
        int rg = ((r >> 1) << 8) + j0 + (r & 1);
        wh1[idx] = Whh[(1024 + rg) * 256 + c];
        wh2[idx] = Whh[(2048 + rg) * 256 + c];
        wi1[idx] = Wihr[rg * 256 + c];
        wi2[idx] = Wihr[(1024 + rg) * 256 + c];
    }
    for (int idx = tid; idx < 512; idx += TPB) {
        int u = idx >> 8, c = idx & 255;
        w1r[idx] = W1[(j0 + u) * 384 + c];
    }
    for (int idx = tid; idx < 33 * 256; idx += TPB) w2s[idx] = W2[idx];
    for (int idx = tid; idx < 256; idx += TPB) {
        h0s[idx] = h0in[idx];
        h1s[idx] = h0in[256 + idx];
        h2s[idx] = h0in[512 + idx];
    }
    if (tid < 8) {
        int rg = ((tid >> 1) << 8) + j0 + (tid & 1);
        biasA[tid] = bih[rg] + bhh[rg];
        biasB[tid] = bih[1024 + rg] + bhh[1024 + rg];
        biasC[tid] = bih[2048 + rg] + bhh[2048 + rg];
    }
    if (tid < 2)  b1r[tid] = b1[j0 + tid];
    if (tid < 33) b2s[tid] = b2[tid];

    float cA = 0.f, cB = 0.f, cC = 0.f;     // cell states in warp0 lanes 0,1
    if (tid < 2) {
        cA = c0in[j0 + tid];
        cB = c0in[256 + j0 + tid];
        cC = c0in[512 + j0 + tid];
    }
    int ch = 0;
    __syncthreads();

    // ---- Embed-projection table: tbl[v*8 + r] = Wih0_row_r . emb[v] ----
    for (int v = 0; v < 33; v++) {
        float s = wreduce(dot256(l0w + wid * 512, embed_g + v * 256, lane));
        if (lane == 0) tbl[v * 8 + wid] = s;
    }
    // ---- Initial recurrent partials from h(t=0) ----
    {
        float s0 = dot256(l0w + wid * 512 + 256, h0s, lane);
        float s1 = dot256(wh1 + wid * 256, h1s, lane);
        float s2 = dot256(wh2 + wid * 256, h2s, lane);
        s0 = wreduce(s0); s1 = wreduce(s1); s2 = wreduce(s2);
        if (lane == 0) {
            pA[wid] = s0 + biasA[wid];
            pB[wid] = s1 + biasB[wid];
            pC[wid] = s2 + biasC[wid];
        }
    }
    __syncthreads();

    // ---- Precomputed output addresses: 264 elems (8 rows x 33) ----
    float* outp0;
    float* outp1 = 0;
    {
        int bl0 = tid / 33;
        outp0 = out + (size_t)(j0 * 4 + bl0) * T_STEPS * 33 + (tid - bl0 * 33);
        if (tid < 8) {
            int e = 256 + tid, bl1 = e / 33;
            outp1 = out + (size_t)(j0 * 4 + bl1) * T_STEPS * 33 + (e - bl1 * 33);
        }
    }
    const int pv0 = tid - (tid / 33) * 33;
    const int pv1 = (256 + tid) - ((256 + tid) / 33) * 33;

    for (int t = 0; t < T_STEPS; t++) {
        const unsigned seq = (unsigned)(t + 1);

        if (wid >= 4) {
            // ===== Poller crew: sample h1 from step start (poll-ahead) =====
            pollslot(g_h1buf, h1s, seq, (wid - 4) * 32 + lane);
            BAR_ARRIVE(2, 256);            // hand h1s to compute crew, move on
            pollslot(g_rbuf, rs, seq, (wid - 4) * 32 + lane);
            BAR_SYNC(3, 256);              // rendezvous: rs ready for all
        } else {
            // ===== Phase A: warp0 only — table lookup + cell, no barriers =====
            if (wid == 0) {
                float v = 0.f;
                if (lane < 8) {
                    float g = tbl[ch * 8 + lane] + pA[lane];
                    v = (lane == 4 || lane == 5) ? ftanh(g) : fsig(g);
                }
                int u = lane & 1;
                float ig = __shfl_sync(FULLM, v, u);
                float fg = __shfl_sync(FULLM, v, 2 + u);
                float gg = __shfl_sync(FULLM, v, 4 + u);
                float og = __shfl_sync(FULLM, v, 6 + u);
                float h = 0.f;
                if (lane < 2) {
                    cA = fg * cA + ig * gg;
                    h  = og * ftanh(cA);
                }
                float hb = __shfl_sync(FULLM, h, 1);
                if (lane == 0) stv4(&g_h0buf[k * CSTRIDE], h, hb, seq);
            }
            // gather h0 (warps 0-3; warps 1-3 were already free to poll)
            pollslot(g_h0buf, h0s, seq, wid * 32 + lane);
            BAR_SYNC(1, 128);

            // ===== Phase B gates: warp w owns gate w (rows 2w, 2w+1) =====
            {
                int r0 = 2 * wid, r1 = r0 + 1;
                float s0 = dot256(wi1 + r0 * 256, h0s, lane);
                float s1 = dot256(wi1 + r1 * 256, h0s, lane);
                wreduce2(s0, s1);
                if (lane == 0) {
                    float g0 = s0 + pB[r0], g1 = s1 + pB[r1];
                    gT[r0] = (wid == 2) ? ftanh(g0) : fsig(g0);
                    gT[r1] = (wid == 2) ? ftanh(g1) : fsig(g1);
                }
            }
            BAR_SYNC(1, 128);
            if (wid == 0) {
                float h = 0.f;
                if (lane < 2) {
                    cB = gT[2 + lane] * cB + gT[lane] * gT[4 + lane];
                    h  = gT[6 + lane] * ftanh(cB);
                }
                float hb = __shfl_sync(FULLM, h, 1);
                if (lane == 0) stv4(&g_h1buf[k * CSTRIDE], h, hb, seq);
            }
            BAR_SYNC(2, 256);              // wait: pollers delivered h1s

            // ===== Phase C gates on h1s =====
            {
                int r0 = 2 * wid, r1 = r0 + 1;
                float s0 = dot256(wi2 + r0 * 256, h1s, lane);
                float s1 = dot256(wi2 + r1 * 256, h1s, lane);
                wreduce2(s0, s1);
                if (lane == 0) {
                    float g0 = s0 + pC[r0], g1 = s1 + pC[r1];
                    gT[r0] = (wid == 2) ? ftanh(g0) : fsig(g0);
                    gT[r1] = (wid == 2) ? ftanh(g1) : fsig(g1);
                }
            }
            BAR_SYNC(1, 128);
            if (wid == 0) {
                float h = 0.f;
                if (lane < 2) {
                    cC = gT[2 + lane] * cC + gT[lane] * gT[4 + lane];
                    h  = gT[6 + lane] * ftanh(cC);
                }
                float hb = __shfl_sync(FULLM, h, 1);
                if (lane == 0) stv4(&g_h2buf[k * CSTRIDE], h, hb, seq);
            }
            // gather h2 (warps 0-3)
            pollslot(g_h2buf, h2s, seq, wid * 32 + lane);
            BAR_SYNC(1, 128);

            // ===== Phase D: warp0 r rows; warps 1-3 next-step partials =====
            if (wid == 0) {
                float s0 = dot256(w1r, h2s, lane);
                float s1 = dot256(w1r + 256, h2s, lane);
                wreduce2(s0, s1);
                if (lane == 0) {
                    float r0 = fmaxf(s0 + b1r[0], 0.f);
                    float r1 = fmaxf(s1 + b1r[1], 0.f);
                    stv4(&g_rbuf[k * CSTRIDE], r0, r1, seq);
                }
            } else if (wid == 1) {
                float a0 = dot256(l0w + 0 * 512 + 256, h0s, lane);
                float a1 = dot256(l0w + 1 * 512 + 256, h0s, lane);
                float a2 = dot256(l0w + 2 * 512 + 256, h0s, lane);
                float a3 = dot256(l0w + 3 * 512 + 256, h0s, lane);
                wreduce4(a0, a1, a2, a3);
                float a4 = dot256(l0w + 4 * 512 + 256, h0s, lane);
                float a5 = dot256(l0w + 5 * 512 + 256, h0s, lane);
                float a6 = dot256(l0w + 6 * 512 + 256, h0s, lane);
                float a7 = dot256(l0w + 7 * 512 + 256, h0s, lane);
                wreduce4(a4, a5, a6, a7);
                if (lane == 0) {
                    pA[0] = a0 + biasA[0]; pA[1] = a1 + biasA[1];
                    pA[2] = a2 + biasA[2]; pA[3] = a3 + biasA[3];
                    pA[4] = a4 + biasA[4]; pA[5] = a5 + biasA[5];
                    pA[6] = a6 + biasA[6]; pA[7] = a7 + biasA[7];
                }
            } else if (wid == 2) {
                float a0 = dot256(wh1 + 0 * 256, h1s, lane);
                float a1 = dot256(wh1 + 1 * 256, h1s, lane);
                float a2 = dot256(wh1 + 2 * 256, h1s, lane);
                float a3 = dot256(wh1 + 3 * 256, h1s, lane);
                wreduce4(a0, a1, a2, a3);
                float a4 = dot256(wh1 + 4 * 256, h1s, lane);
                float a5 = dot256(wh1 + 5 * 256, h1s, lane);
                float a6 = dot256(wh1 + 6 * 256, h1s, lane);
                float a7 = dot256(wh1 + 7 * 256, h1s, lane);
                wreduce4(a4, a5, a6, a7);
                if (lane == 0) {
                    pB[0] = a0 + biasB[0]; pB[1] = a1 + biasB[1];
                    pB[2] = a2 + biasB[2]; pB[3] = a3 + biasB[3];
                    pB[4] = a4 + biasB[4]; pB[5] = a5 + biasB[5];
                    pB[6] = a6 + biasB[6]; pB[7] = a7 + biasB[7];
                }
            } else {
                float a0 = dot256(wh2 + 0 * 256, h2s, lane);
                float a1 = dot256(wh2 + 1 * 256, h2s, lane);
                float a2 = dot256(wh2 + 2 * 256, h2s, lane);
                float a3 = dot256(wh2 + 3 * 256, h2s, lane);
                wreduce4(a0, a1, a2, a3);
                float a4 = dot256(wh2 + 4 * 256, h2s, lane);
                float a5 = dot256(wh2 + 5 * 256, h2s, lane);
                float a6 = dot256(wh2 + 6 * 256, h2s, lane);
                float a7 = dot256(wh2 + 7 * 256, h2s, lane);
                wreduce4(a4, a5, a6, a7);
                if (lane == 0) {
                    pC[0] = a0 + biasC[0]; pC[1] = a1 + biasC[1];
                    pC[2] = a2 + biasC[2]; pC[3] = a3 + biasC[3];
                    pC[4] = a4 + biasC[4]; pC[5] = a5 + biasC[5];
                    pC[6] = a6 + biasC[6]; pC[7] = a7 + biasC[7];
                }
            }
            BAR_SYNC(3, 256);              // rendezvous: rs ready
        }

        // ===== Phase E: classifier on all 8 warps, argmax, output =====
        {
            float s0 = dot256(w2s + wid * 256, rs, lane);
            float s1 = dot256(w2s + (wid + 8) * 256, rs, lane);
            float s2 = dot256(w2s + (wid + 16) * 256, rs, lane);
            float s3 = dot256(w2s + (wid + 24) * 256, rs, lane);
            if (wid == 0) {
                float s4 = dot256(w2s + 32 * 256, rs, lane);
                wreduce5(s0, s1, s2, s3, s4);
                if (lane == 0) pred[32] = s4 + b2s[32];
            } else {
                wreduce4(s0, s1, s2, s3);
            }
            if (lane == 0) {
                pred[wid]      = s0 + b2s[wid];
                pred[wid + 8]  = s1 + b2s[wid + 8];
                pred[wid + 16] = s2 + b2s[wid + 16];
                pred[wid + 24] = s3 + b2s[wid + 24];
            }
        }
        __syncthreads();
        {
            float best = pred[0];
            int bi = 0;
#pragma unroll
            for (int v = 1; v < 33; v++) {
                float p = pred[v];
                if (p > best) { best = p; bi = v; }
            }
            ch = bi;   // bit-identical across CTAs -> uniform feedback
        }
        *outp0 = pred[pv0];
        outp0 += 33;
        if (outp1) {
            *outp1 = pred[pv1];
            outp1 += 33;
        }
    }
}

extern "C" void kernel_launch(void* const* d_in, const int* in_sizes, int n_in,
                              void* d_out, int out_size) {
    // metadata order: labels, embed, Wih0, Wih_rest, Whh, bih, bhh,
    //                 W1, b1, W2, b2, h0, c0
    const float* embed = (const float*)d_in[1];
    const float* Wih0  = (const float*)d_in[2];
    const float* Wihr  = (const float*)d_in[3];
    const float* Whh   = (const float*)d_in[4];
    const float* bih   = (const float*)d_in[5];
    const float* bhh   = (const float*)d_in[6];
    const float* W1    = (const float*)d_in[7];
    const float* b1    = (const float*)d_in[8];
    const float* W2    = (const float*)d_in[9];
    const float* b2    = (const float*)d_in[10];
    const float* h0    = (const float*)d_in[11];
    const float* c0    = (const float*)d_in[12];
    float* out = (float*)d_out;

    size_t smem = (size_t)SMEM_FLOATS * sizeof(float);
    cudaFuncSetAttribute(speller_kernel,
                         cudaFuncAttributeMaxDynamicSharedMemorySize,
                         (int)smem);
    speller_kernel<<<G, TPB, smem>>>(embed, Wih0, Wihr, Whh, bih, bhh,
                                     W1, b1, W2, b2, h0, c0, out);
}

// round 13
// speedup vs baseline: 1.0177x; 1.0177x over previous
#include <cuda_runtime.h>

#define G 128
#define TPB 256
#define T_STEPS 220
#define CSTRIDE 16   // float4s per slot: 256B -> spreads L2 slice hash bits
#define FULLM 0xffffffffu

// Seqlock exchange buffers: {val0, val1, seq, seq} per CTA, 256B-strided
// (round-6 proven layout; data + flag in one 16B volatile load).
__device__ float4 g_h0buf[G * CSTRIDE];
__device__ float4 g_h1buf[G * CSTRIDE];
__device__ float4 g_h2buf[G * CSTRIDE];
__device__ float4 g_rbuf [G * CSTRIDE];

__device__ __forceinline__ void ldv4(const float4* p, float& a, float& b,
                                     unsigned& s0, unsigned& s1) {
    unsigned x, y;
    asm volatile("ld.volatile.global.v4.b32 {%0,%1,%2,%3}, [%4];"
                 : "=r"(x), "=r"(y), "=r"(s0), "=r"(s1) : "l"(p));
    a = __uint_as_float(x);
    b = __uint_as_float(y);
}
__device__ __forceinline__ void stv4(float4* p, float a, float b, unsigned s) {
    asm volatile("st.volatile.global.v4.b32 [%0], {%1,%2,%3,%4};"
                 :: "l"(p), "r"(__float_as_uint(a)), "r"(__float_as_uint(b)),
                    "r"(s), "r"(s));
}
__device__ __forceinline__ float wreduce(float v) {
#pragma unroll
    for (int m = 16; m >= 1; m >>= 1) v += __shfl_xor_sync(FULLM, v, m);
    return v;
}
__device__ __forceinline__ void wreduce2(float& a, float& b) {
#pragma unroll
    for (int m = 16; m >= 1; m >>= 1) {
        a += __shfl_xor_sync(FULLM, a, m);
        b += __shfl_xor_sync(FULLM, b, m);
    }
}
__device__ __forceinline__ void wreduce5(float& a, float& b, float& c,
                                         float& d, float& e) {
#pragma unroll
    for (int m = 16; m >= 1; m >>= 1) {
        a += __shfl_xor_sync(FULLM, a, m);
        b += __shfl_xor_sync(FULLM, b, m);
        c += __shfl_xor_sync(FULLM, c, m);
        d += __shfl_xor_sync(FULLM, d, m);
        e += __shfl_xor_sync(FULLM, e, m);
    }
}
// Fast activations (~1e-6 rel err; argmax-safe vs observed 3e-7 pipeline err)
__device__ __forceinline__ float fsig(float x) {
    return __fdividef(1.0f, 1.0f + __expf(-x));
}
__device__ __forceinline__ float ftanh(float x) {
    return 1.0f - __fdividef(2.0f, __expf(2.0f * x) + 1.0f);
}
__device__ __forceinline__ float dot256(const float* w, const float* x, int lane) {
    const float4* w4 = (const float4*)w;
    const float4* x4 = (const float4*)x;
    float s = 0.f;
#pragma unroll
    for (int i = 0; i < 2; i++) {
        float4 a = w4[i * 32 + lane], b = x4[i * 32 + lane];
        s += a.x * b.x + a.y * b.y + a.z * b.z + a.w * b.w;
    }
    return s;
}
// Gather with PREDICATED re-poll: satisfied lanes stop issuing loads,
// cutting steady-state L2 poll traffic ~10x (queueing-relief experiment).
// Slot layout and discovery path otherwise identical to round 6.
__device__ __forceinline__ void gather(const float4* buf, float* dst,
                                       unsigned seq, int wid, int lane) {
    if (wid < 4) {
        int s = wid * 32 + lane;
        const float4* p = buf + (size_t)s * CSTRIDE;
        float a = 0.f, b = 0.f;
        unsigned s0, s1;
        bool ok = false;
        do {
            if (!ok) {
                ldv4(p, a, b, s0, s1);
                ok = (s0 == seq) && (s1 == seq);
            }
        } while (!__all_sync(FULLM, ok));
        dst[2 * s]     = a;
        dst[2 * s + 1] = b;
    }
    __syncthreads();
}

// SMEM layout (floats)
#define OFF_L0W   0       // 8 x 512  layer0 [Wih(:,0:256) | Whh]
#define OFF_WH1   4096    // 8 x 256
#define OFF_WH2   6144
#define OFF_WI1   8192
#define OFF_WI2   10240
#define OFF_W1R   12288   // 2 x 256
#define OFF_W2S   12800   // 33 x 256
#define OFF_TBL   21248   // 33 x 8 embed-projection table
#define OFF_H0S   21512   // 256
#define OFF_H1S   21768
#define OFF_H2S   22024
#define OFF_RS    22280
#define OFF_GT    22536   // 8
#define OFF_PA    22544   // 8
#define OFF_PB    22552
#define OFF_PC    22560
#define OFF_PRED  22568   // 33 (+pad)
#define OFF_BA    22604   // 8
#define OFF_BB    22612
#define OFF_BC    22620
#define OFF_B1R   22628   // 2
#define OFF_B2S   22630   // 33
#define SMEM_FLOATS 22664

__global__ void __launch_bounds__(TPB, 1)
speller_kernel(const float* __restrict__ embed_g,
               const float* __restrict__ Wih0,
               const float* __restrict__ Wihr,
               const float* __restrict__ Whh,
               const float* __restrict__ bih,
               const float* __restrict__ bhh,
               const float* __restrict__ W1,
               const float* __restrict__ b1,
               const float* __restrict__ W2,
               const float* __restrict__ b2,
               const float* __restrict__ h0in,
               const float* __restrict__ c0in,
               float* __restrict__ out)
{
    extern __shared__ float sm[];
    float* l0w  = sm + OFF_L0W;
    float* wh1  = sm + OFF_WH1;
    float* wh2  = sm + OFF_WH2;
    float* wi1  = sm + OFF_WI1;
    float* wi2  = sm + OFF_WI2;
    float* w1r  = sm + OFF_W1R;
    float* w2s  = sm + OFF_W2S;
    float* tbl  = sm + OFF_TBL;
    float* h0s  = sm + OFF_H0S;
    float* h1s  = sm + OFF_H1S;
    float* h2s  = sm + OFF_H2S;
    float* rs   = sm + OFF_RS;
    float* gT   = sm + OFF_GT;
    float* pA   = sm + OFF_PA;
    float* pB   = sm + OFF_PB;
    float* pC   = sm + OFF_PC;
    float* pred = sm + OFF_PRED;
    float* biasA = sm + OFF_BA;
    float* biasB = sm + OFF_BB;
    float* biasC = sm + OFF_BC;
    float* b1r  = sm + OFF_B1R;
    float* b2s  = sm + OFF_B2S;

    const int tid  = threadIdx.x;
    const int wid  = tid >> 5;
    const int lane = tid & 31;
    const int k    = blockIdx.x;
    const int j0   = 2 * k;          // this CTA's hidden-unit pair

    // ---- One-time weight staging (ctx columns are all-zero: dropped) ----
    // local gate row r = gate*2 + u  (i:0,1  f:2,3  g:4,5  o:6,7)
    for (int idx = tid; idx < 8 * 512; idx += TPB) {
        int r = idx >> 9, c = idx & 511;
        int rg = ((r >> 1) << 8) + j0 + (r & 1);
        l0w[idx] = (c < 256) ? Wih0[rg * 384 + c] : Whh[rg * 256 + (c - 256)];
    }
    for (int idx = tid; idx < 8 * 256; idx += TPB) {
        int r = idx >> 8, c = idx & 255;
        int rg = ((r >> 1) << 8) + j0 + (r & 1);
        wh1[idx] = Whh[(1024 + rg) * 256 + c];
        wh2[idx] = Whh[(2048 + rg) * 256 + c];
        wi1[idx] = Wihr[rg * 256 + c];
        wi2[idx] = Wihr[(1024 + rg) * 256 + c];
    }
    for (int idx = tid; idx < 512; idx += TPB) {
        int u = idx >> 8, c = idx & 255;
        w1r[idx] = W1[(j0 + u) * 384 + c];
    }
    for (int idx = tid; idx < 33 * 256; idx += TPB) w2s[idx] = W2[idx];
    for (int idx = tid; idx < 256; idx += TPB) {
        h0s[idx] = h0in[idx];
        h1s[idx] = h0in[256 + idx];
        h2s[idx] = h0in[512 + idx];
    }
    if (tid < 8) {
        int rg = ((tid >> 1) << 8) + j0 + (tid & 1);
        biasA[tid] = bih[rg] + bhh[rg];
        biasB[tid] = bih[1024 + rg] + bhh[1024 + rg];
        biasC[tid] = bih[2048 + rg] + bhh[2048 + rg];
    }
    if (tid < 2)  b1r[tid] = b1[j0 + tid];
    if (tid < 33) b2s[tid] = b2[tid];

    float cA = 0.f, cB = 0.f, cC = 0.f;     // cell states in warp0 lanes 0,1
    if (tid < 2) {
        cA = c0in[j0 + tid];
        cB = c0in[256 + j0 + tid];
        cC = c0in[512 + j0 + tid];
    }
    int ch = 0;
    __syncthreads();

    // ---- Embed-projection table: tbl[v*8 + r] = Wih0_row_r . emb[v] ----
    for (int v = 0; v < 33; v++) {
        float s = wreduce(dot256(l0w + wid * 512, embed_g + v * 256, lane));
        if (lane == 0) tbl[v * 8 + wid] = s;
    }
    // ---- Initial recurrent partials from h(t=0) ----
    {
        float s0 = dot256(l0w + wid * 512 + 256, h0s, lane);
        float s1 = dot256(wh1 + wid * 256, h1s, lane);
        float s2 = dot256(wh2 + wid * 256, h2s, lane);
        s0 = wreduce(s0); s1 = wreduce(s1); s2 = wreduce(s2);
        if (lane == 0) {
            pA[wid] = s0 + biasA[wid];
            pB[wid] = s1 + biasB[wid];
            pC[wid] = s2 + biasC[wid];
        }
    }
    __syncthreads();

    // ---- Precomputed output addresses: 264 elems (8 rows x 33) ----
    float* outp0;
    float* outp1 = 0;
    {
        int bl0 = tid / 33;
        outp0 = out + (size_t)(j0 * 4 + bl0) * T_STEPS * 33 + (tid - bl0 * 33);
        if (tid < 8) {
            int e = 256 + tid, bl1 = e / 33;
            outp1 = out + (size_t)(j0 * 4 + bl1) * T_STEPS * 33 + (e - bl1 * 33);
        }
    }
    const int pv0 = tid - (tid / 33) * 33;
    const int pv1 = (256 + tid) - ((256 + tid) / 33) * 33;

    for (int t = 0; t < T_STEPS; t++) {
        const unsigned seq = (unsigned)(t + 1);

        // ===== Phase A: warp0 only — table lookup + cell, no barriers =====
        if (wid == 0) {
            float v = 0.f;
            if (lane < 8) {
                float g = tbl[ch * 8 + lane] + pA[lane];
                v = (lane == 4 || lane == 5) ? ftanh(g) : fsig(g);
            }
            int u = lane & 1;
            float ig = __shfl_sync(FULLM, v, u);
            float fg = __shfl_sync(FULLM, v, 2 + u);
            float gg = __shfl_sync(FULLM, v, 4 + u);
            float og = __shfl_sync(FULLM, v, 6 + u);
            float h = 0.f;
            if (lane < 2) {
                cA = fg * cA + ig * gg;
                h  = og * ftanh(cA);
            }
            float hb = __shfl_sync(FULLM, h, 1);
            if (lane == 0) stv4(&g_h0buf[k * CSTRIDE], h, hb, seq);
        }

        // ===== Phase B: wait all h0, layer1 gates =====
        gather(g_h0buf, h0s, seq, wid, lane);
        {
            float s = wreduce(dot256(wi1 + wid * 256, h0s, lane));
            if (lane == 0) {
                float g = s + pB[wid];
                gT[wid] = (wid == 4 || wid == 5) ? ftanh(g) : fsig(g);
            }
        }
        __syncthreads();
        if (wid == 0) {
            float h = 0.f;
            if (lane < 2) {
                cB = gT[2 + lane] * cB + gT[lane] * gT[4 + lane];
                h  = gT[6 + lane] * ftanh(cB);
            }
            float hb = __shfl_sync(FULLM, h, 1);
            if (lane == 0) stv4(&g_h1buf[k * CSTRIDE], h, hb, seq);
        }

        // ===== Phase C: wait all h1, layer2 gates =====
        gather(g_h1buf, h1s, seq, wid, lane);
        {
            float s = wreduce(dot256(wi2 + wid * 256, h1s, lane));
            if (lane == 0) {
                float g = s + pC[wid];
                gT[wid] = (wid == 4 || wid == 5) ? ftanh(g) : fsig(g);
            }
        }
        __syncthreads();
        if (wid == 0) {
            float h = 0.f;
            if (lane < 2) {
                cC = gT[2 + lane] * cC + gT[lane] * gT[4 + lane];
                h  = gT[6 + lane] * ftanh(cC);
            }
            float hb = __shfl_sync(FULLM, h, 1);
            if (lane == 0) stv4(&g_h2buf[k * CSTRIDE], h, hb, seq);
        }

        // ===== Phase D: wait all h2; warp0 publishes both r rows =====
        gather(g_h2buf, h2s, seq, wid, lane);
        if (wid == 0) {
            float s0 = dot256(w1r, h2s, lane);
            float s1 = dot256(w1r + 256, h2s, lane);
            wreduce2(s0, s1);
            if (lane == 0) {
                float r0 = fmaxf(s0 + b1r[0], 0.f);
                float r1 = fmaxf(s1 + b1r[1], 0.f);
                stv4(&g_rbuf[k * CSTRIDE], r0, r1, seq);
            }
        }
        // Overlap (round-6 placement): next step's recurrent partials
        {
            float s0 = dot256(l0w + wid * 512 + 256, h0s, lane);
            float s1 = dot256(wh1 + wid * 256, h1s, lane);
            float s2 = dot256(wh2 + wid * 256, h2s, lane);
            s0 = wreduce(s0); s1 = wreduce(s1); s2 = wreduce(s2);
            if (lane == 0) {
                pA[wid] = s0 + biasA[wid];
                pB[wid] = s1 + biasB[wid];
                pC[wid] = s2 + biasC[wid];
            }
        }

        // ===== Phase E: wait all r, redundant classifier + argmax + out =====
        gather(g_rbuf, rs, seq, wid, lane);
        {
            float s0 = dot256(w2s + wid * 256, rs, lane);
            float s1 = dot256(w2s + (wid + 8) * 256, rs, lane);
            float s2 = dot256(w2s + (wid + 16) * 256, rs, lane);
            float s3 = dot256(w2s + (wid + 24) * 256, rs, lane);
            if (wid == 0) {
                float s4 = dot256(w2s + 32 * 256, rs, lane);
                wreduce5(s0, s1, s2, s3, s4);   // row 32 interleaved
                if (lane == 0) pred[32] = s4 + b2s[32];
            } else {
#pragma unroll
                for (int m = 16; m >= 1; m >>= 1) {
                    s0 += __shfl_xor_sync(FULLM, s0, m);
                    s1 += __shfl_xor_sync(FULLM, s1, m);
                    s2 += __shfl_xor_sync(FULLM, s2, m);
                    s3 += __shfl_xor_sync(FULLM, s3, m);
                }
            }
            if (lane == 0) {
                pred[wid]      = s0 + b2s[wid];
                pred[wid + 8]  = s1 + b2s[wid + 8];
                pred[wid + 16] = s2 + b2s[wid + 16];
                pred[wid + 24] = s3 + b2s[wid + 24];
            }
        }
        __syncthreads();
        {
            float best = pred[0];
            int bi = 0;
#pragma unroll
            for (int v = 1; v < 33; v++) {
                float p = pred[v];
                if (p > best) { best = p; bi = v; }
            }
            ch = bi;   // bit-identical across CTAs -> uniform feedback
        }
        // Output via hoisted pointers (one STG each; +33 floats per step)
        *outp0 = pred[pv0];
        outp0 += 33;
        if (outp1) {
            *outp1 = pred[pv1];
            outp1 += 33;
        }
    }
}

extern "C" void kernel_launch(void* const* d_in, const int* in_sizes, int n_in,
                              void* d_out, int out_size) {
    // metadata order: labels, embed, Wih0, Wih_rest, Whh, bih, bhh,
    //                 W1, b1, W2, b2, h0, c0
    const float* embed = (const float*)d_in[1];
    const float* Wih0  = (const float*)d_in[2];
    const float* Wihr  = (const float*)d_in[3];
    const float* Whh   = (const float*)d_in[4];
    const float* bih   = (const float*)d_in[5];
    const float* bhh   = (const float*)d_in[6];
    const float* W1    = (const float*)d_in[7];
    const float* b1    = (const float*)d_in[8];
    const float* W2    = (const float*)d_in[9];
    const float* b2    = (const float*)d_in[10];
    const float* h0    = (const float*)d_in[11];
    const float* c0    = (const float*)d_in[12];
    float* out = (float*)d_out;

    size_t smem = (size_t)SMEM_FLOATS * sizeof(float);
    cudaFuncSetAttribute(speller_kernel,
                         cudaFuncAttributeMaxDynamicSharedMemorySize,
                         (int)smem);
    speller_kernel<<<G, TPB, smem>>>(embed, Wih0, Wihr, Whh, bih, bhh,
                                     W1, b1, W2, b2, h0, c0, out);
}